// round 3
// baseline (speedup 1.0000x reference)
#include <cuda_runtime.h>
#include <cstdint>
#include <cstddef>

// Problem constants
#define BROWS 16384
#define INDIM 1024
#define HID   4096
#define ODIM  384
#define NGRP  6
#define POOL  64
#define TOPK  2

// ---------------- scratch (device globals; no allocation allowed) ----------------
__device__ float g_h1[(size_t)BROWS * HID];     // 256 MB
__device__ float g_h2[(size_t)BROWS * HID];     // 256 MB

// ---------------- helpers ----------------
__device__ __forceinline__ float tf32r(float x) {
    uint32_t u;
    asm("cvt.rna.tf32.f32 %0, %1;" : "=r"(u) : "f"(x));
    return __uint_as_float(u);
}

__device__ __forceinline__ double gelu_tanh_d(double x) {
    double x3 = x * x * x;
    double t = tanh(0.7978845608028654 * (x + 0.044715 * x3));
    return 0.5 * x * (1.0 + t);
}

__device__ __forceinline__ double sig2_d(double x) {
    return 2.0 / (1.0 + exp(-x));
}

// ---------------- 3xTF32 GEMM: C[M,N] = act(A[M,K] @ B[K,N] + bias) ----------------
// CTA tile 128x128, BK=32, 256 threads (8 warps, warp tile 64x32), 2-stage cp.async.
// Each fp32 operand is split a = a_hi + a_lo (tf32 each). Main product a_hi*b_hi
// accumulates in c[]; cross terms a_hi*b_lo + a_lo*b_hi accumulate in s2[] (small
// magnitude -> negligible rounding). a_lo*b_lo (~2^-22 rel) dropped.
// EPI==0: gelu(tanh) in fp64, EPI==1: 2*sigmoid in fp64.
#define SA_PITCH 36
#define SB_PITCH 132
#define SA_STAGE (128 * SA_PITCH)
#define SB_STAGE (32 * SB_PITCH)
#define GEMM_SMEM ((2 * SA_STAGE + 2 * SB_STAGE) * 4)

template <int EPI>
__global__ __launch_bounds__(256, 1) void gemm_3xtf32(
    const float* __restrict__ A, const float* __restrict__ Bw,
    const float* __restrict__ bias, float* __restrict__ C,
    int N, int K)
{
    extern __shared__ float smem[];
    float* sA = smem;                 // [2][128][36]
    float* sB = smem + 2 * SA_STAGE;  // [2][32][132]

    const int tid  = threadIdx.x;
    const int lane = tid & 31;
    const int warp = tid >> 5;
    const int wm = warp & 1;      // 2 warp rows (64 each)
    const int wn = warp >> 1;     // 4 warp cols (32 each)
    const int gid = lane >> 2;    // 0..7
    const int tq  = lane & 3;     // 0..3

    const int m0 = blockIdx.y * 128;
    const int n0 = blockIdx.x * 128;

    const int arow = tid >> 3;          // 0..31
    const int acol = (tid & 7) * 4;     // 0..28
    const int brow = tid >> 5;          // 0..7
    const int bcol = (tid & 31) * 4;    // 0..124

    const float* Ag = A + (size_t)(m0 + arow) * K + acol;
    const float* Bg = Bw + (size_t)brow * N + (n0 + bcol);

    uint32_t sAbase = (uint32_t)__cvta_generic_to_shared(sA);
    uint32_t sBbase = (uint32_t)__cvta_generic_to_shared(sB);

    const int nk = K >> 5;

    auto load_tile = [&](int kt, int s) {
        uint32_t aS = sAbase + (uint32_t)s * (SA_STAGE * 4);
        uint32_t bS = sBbase + (uint32_t)s * (SB_STAGE * 4);
        const float* ag = Ag + kt;
        const float* bg = Bg + (size_t)kt * N;
#pragma unroll
        for (int p = 0; p < 4; p++) {
            uint32_t d = aS + (uint32_t)(((arow + p * 32) * SA_PITCH + acol) * 4);
            asm volatile("cp.async.cg.shared.global [%0], [%1], 16;\n"
                         :: "r"(d), "l"(ag + (size_t)p * 32 * K) : "memory");
        }
#pragma unroll
        for (int p = 0; p < 4; p++) {
            uint32_t d = bS + (uint32_t)(((brow + p * 8) * SB_PITCH + bcol) * 4);
            asm volatile("cp.async.cg.shared.global [%0], [%1], 16;\n"
                         :: "r"(d), "l"(bg + (size_t)p * 8 * N) : "memory");
        }
        asm volatile("cp.async.commit_group;\n" ::: "memory");
    };

    float c[4][4][4];   // main: hi*hi
    float s2[4][4][4];  // cross: hi*lo + lo*hi
#pragma unroll
    for (int a = 0; a < 4; a++)
#pragma unroll
        for (int b = 0; b < 4; b++)
#pragma unroll
            for (int d = 0; d < 4; d++) { c[a][b][d] = 0.0f; s2[a][b][d] = 0.0f; }

    load_tile(0, 0);

    for (int ki = 0; ki < nk; ki++) {
        const int st = ki & 1;
        if (ki + 1 < nk) {
            load_tile((ki + 1) << 5, (ki + 1) & 1);
            asm volatile("cp.async.wait_group 1;\n" ::: "memory");
        } else {
            asm volatile("cp.async.wait_group 0;\n" ::: "memory");
        }
        __syncthreads();

        const float* As = sA + st * SA_STAGE;
        const float* Bs = sB + st * SB_STAGE;

#pragma unroll
        for (int ks = 0; ks < 4; ks++) {
            const int k0 = ks * 8;
            uint32_t ah[4][4], al[4][4];
            uint32_t bh[4][2], bl[4][2];
#pragma unroll
            for (int mi = 0; mi < 4; mi++) {
                const int r = wm * 64 + mi * 16 + gid;
                const float* ap = As + r * SA_PITCH + (k0 + tq);
                float v0 = ap[0];
                float v1 = ap[8 * SA_PITCH];
                float v2 = ap[4];
                float v3 = ap[8 * SA_PITCH + 4];
                float h0 = tf32r(v0), h1v = tf32r(v1), h2v = tf32r(v2), h3 = tf32r(v3);
                ah[mi][0] = __float_as_uint(h0);
                ah[mi][1] = __float_as_uint(h1v);
                ah[mi][2] = __float_as_uint(h2v);
                ah[mi][3] = __float_as_uint(h3);
                al[mi][0] = __float_as_uint(tf32r(v0 - h0));
                al[mi][1] = __float_as_uint(tf32r(v1 - h1v));
                al[mi][2] = __float_as_uint(tf32r(v2 - h2v));
                al[mi][3] = __float_as_uint(tf32r(v3 - h3));
            }
#pragma unroll
            for (int ni = 0; ni < 4; ni++) {
                const int cN = wn * 32 + ni * 8 + gid;
                const float* bp = Bs + (k0 + tq) * SB_PITCH + cN;
                float v0 = bp[0];
                float v1 = bp[4 * SB_PITCH];
                float h0 = tf32r(v0), h1v = tf32r(v1);
                bh[ni][0] = __float_as_uint(h0);
                bh[ni][1] = __float_as_uint(h1v);
                bl[ni][0] = __float_as_uint(tf32r(v0 - h0));
                bl[ni][1] = __float_as_uint(tf32r(v1 - h1v));
            }
#pragma unroll
            for (int mi = 0; mi < 4; mi++)
#pragma unroll
                for (int ni = 0; ni < 4; ni++) {
                    asm volatile(
                        "mma.sync.aligned.m16n8k8.row.col.f32.tf32.tf32.f32 "
                        "{%0,%1,%2,%3}, {%4,%5,%6,%7}, {%8,%9}, {%0,%1,%2,%3};\n"
                        : "+f"(c[mi][ni][0]), "+f"(c[mi][ni][1]),
                          "+f"(c[mi][ni][2]), "+f"(c[mi][ni][3])
                        : "r"(ah[mi][0]), "r"(ah[mi][1]), "r"(ah[mi][2]), "r"(ah[mi][3]),
                          "r"(bh[ni][0]), "r"(bh[ni][1]));
                    asm volatile(
                        "mma.sync.aligned.m16n8k8.row.col.f32.tf32.tf32.f32 "
                        "{%0,%1,%2,%3}, {%4,%5,%6,%7}, {%8,%9}, {%0,%1,%2,%3};\n"
                        : "+f"(s2[mi][ni][0]), "+f"(s2[mi][ni][1]),
                          "+f"(s2[mi][ni][2]), "+f"(s2[mi][ni][3])
                        : "r"(ah[mi][0]), "r"(ah[mi][1]), "r"(ah[mi][2]), "r"(ah[mi][3]),
                          "r"(bl[ni][0]), "r"(bl[ni][1]));
                    asm volatile(
                        "mma.sync.aligned.m16n8k8.row.col.f32.tf32.tf32.f32 "
                        "{%0,%1,%2,%3}, {%4,%5,%6,%7}, {%8,%9}, {%0,%1,%2,%3};\n"
                        : "+f"(s2[mi][ni][0]), "+f"(s2[mi][ni][1]),
                          "+f"(s2[mi][ni][2]), "+f"(s2[mi][ni][3])
                        : "r"(al[mi][0]), "r"(al[mi][1]), "r"(al[mi][2]), "r"(al[mi][3]),
                          "r"(bh[ni][0]), "r"(bh[ni][1]));
                }
        }
        __syncthreads();
    }

    // epilogue: combine main + cross + bias in fp64, activation in fp64
#pragma unroll
    for (int mi = 0; mi < 4; mi++) {
        const int r0 = m0 + wm * 64 + mi * 16 + gid;
#pragma unroll
        for (int ni = 0; ni < 4; ni++) {
            const int col = n0 + wn * 32 + ni * 8 + tq * 2;
            const double bb0 = (double)bias[col];
            const double bb1 = (double)bias[col + 1];
            double v0 = (double)c[mi][ni][0] + (double)s2[mi][ni][0] + bb0;
            double v1 = (double)c[mi][ni][1] + (double)s2[mi][ni][1] + bb1;
            double v2 = (double)c[mi][ni][2] + (double)s2[mi][ni][2] + bb0;
            double v3 = (double)c[mi][ni][3] + (double)s2[mi][ni][3] + bb1;
            float o0, o1, o2, o3;
            if (EPI == 0) {
                o0 = (float)gelu_tanh_d(v0);
                o1 = (float)gelu_tanh_d(v1);
                o2 = (float)gelu_tanh_d(v2);
                o3 = (float)gelu_tanh_d(v3);
            } else {
                o0 = (float)sig2_d(v0);
                o1 = (float)sig2_d(v1);
                o2 = (float)sig2_d(v2);
                o3 = (float)sig2_d(v3);
            }
            *(float2*)(C + (size_t)r0 * N + col)       = make_float2(o0, o1);
            *(float2*)(C + (size_t)(r0 + 8) * N + col) = make_float2(o2, o3);
        }
    }
}

// ---------------- per-group top-2 (stable, descending — matches jax.lax.top_k) ----------------
__global__ void topk_kernel(const float* __restrict__ coeff,
                            float* __restrict__ tv, float* __restrict__ ti)
{
    int g = blockIdx.x * blockDim.x + threadIdx.x;
    if (g >= BROWS * NGRP) return;
    const int row = g / NGRP;
    const int grp = g - row * NGRP;
    const float* p = coeff + (size_t)row * ODIM + grp * POOL;

    float v1 = -1e30f, v2 = -1e30f;
    int i1 = 0, i2 = 0;
#pragma unroll 8
    for (int i = 0; i < POOL; i++) {
        float v = p[i];
        if (v > v1) { v2 = v1; i2 = i1; v1 = v; i1 = i; }
        else if (v > v2) { v2 = v; i2 = i; }
    }
    const size_t o = (size_t)row * (NGRP * TOPK) + grp * TOPK;
    tv[o]     = v1;
    tv[o + 1] = v2;
    ti[o]     = (float)i1;
    ti[o + 1] = (float)i2;
}

// ---------------- launch ----------------
extern "C" void kernel_launch(void* const* d_in, const int* in_sizes, int n_in,
                              void* d_out, int out_size)
{
    const float* q  = (const float*)d_in[0];
    const float* W1 = (const float*)d_in[1];
    const float* b1 = (const float*)d_in[2];
    const float* W2 = (const float*)d_in[3];
    const float* b2 = (const float*)d_in[4];
    const float* W3 = (const float*)d_in[5];
    const float* b3 = (const float*)d_in[6];
    float* out = (float*)d_out;

    static float *h1 = nullptr, *h2 = nullptr;
    static bool configured = false;
    if (!configured) {
        cudaGetSymbolAddress((void**)&h1, g_h1);
        cudaGetSymbolAddress((void**)&h2, g_h2);
        cudaFuncSetAttribute(gemm_3xtf32<0>, cudaFuncAttributeMaxDynamicSharedMemorySize, GEMM_SMEM);
        cudaFuncSetAttribute(gemm_3xtf32<1>, cudaFuncAttributeMaxDynamicSharedMemorySize, GEMM_SMEM);
        configured = true;
    }

    dim3 blk(256);
    dim3 g12(HID / 128, BROWS / 128);   // (32, 128)
    gemm_3xtf32<0><<<g12, blk, GEMM_SMEM>>>(q,  W1, b1, h1, HID, INDIM);
    gemm_3xtf32<0><<<g12, blk, GEMM_SMEM>>>(h1, W2, b2, h2, HID, HID);

    dim3 g3(ODIM / 128, BROWS / 128);   // (3, 128)
    gemm_3xtf32<1><<<g3, blk, GEMM_SMEM>>>(h2, W3, b3, out, ODIM, HID);

    // top-2 per group; outputs concatenated: coeff | topk_coeff | topk_idx(as float)
    float* tv = out + (size_t)BROWS * ODIM;
    float* ti = tv + (size_t)BROWS * NGRP * TOPK;
    topk_kernel<<<(BROWS * NGRP + 255) / 256, 256>>>(out, tv, ti);
}